// round 1
// baseline (speedup 1.0000x reference)
#include <cuda_runtime.h>
#include <cstddef>

// Problem constants
#define NB    4
#define NSEQ  2048
#define DIMM  512
#define NH    8
#define DHEAD 64
#define QKVC  1536   // 3 * inner

// Scratch (no cudaMalloc allowed)
__device__ float g_qkv[(size_t)NB * NSEQ * QKVC];   // [b, n, 3*inner]
__device__ float g_ao [(size_t)NB * NSEQ * DIMM];   // attention output [b, n, inner]

// ---------------------------------------------------------------------------
// GEMM: C[M,N] = A[M,K] @ B[K,N] (+ bias). 128x128 block tile, BK=8,
// 256 threads, 8x8 register micro-tile per thread.
// ---------------------------------------------------------------------------
template <bool BIAS>
__global__ __launch_bounds__(256) void gemm128(const float* __restrict__ A,
                                               const float* __restrict__ Bm,
                                               const float* __restrict__ bias,
                                               float* __restrict__ C,
                                               int M, int N, int K)
{
    __shared__ float As[8][128];   // [k][m] (A transposed in smem)
    __shared__ float Bs[8][128];   // [k][n]

    const int n0 = blockIdx.x * 128;
    const int m0 = blockIdx.y * 128;
    const int tid = threadIdx.x;
    const int ty = tid >> 4;    // 0..15
    const int tx = tid & 15;    // 0..15

    const int arow = tid >> 1, akf = tid & 1;     // A loader: 128 rows x 2 float4
    const int bkrow = tid >> 5, bnf = tid & 31;   // B loader: 8 rows x 32 float4

    const float* aptr = A + (size_t)(m0 + arow) * K + akf * 4;
    const float* bptr = Bm + (size_t)bkrow * N + n0 + bnf * 4;

    float acc[8][8] = {};

    for (int k0 = 0; k0 < K; k0 += 8) {
        float4 a = *(const float4*)(aptr + k0);
        As[akf * 4 + 0][arow] = a.x;
        As[akf * 4 + 1][arow] = a.y;
        As[akf * 4 + 2][arow] = a.z;
        As[akf * 4 + 3][arow] = a.w;
        *(float4*)&Bs[bkrow][bnf * 4] = *(const float4*)(bptr + (size_t)k0 * N);
        __syncthreads();

#pragma unroll
        for (int k = 0; k < 8; ++k) {
            float av[8], bv[8];
            *(float4*)&av[0] = *(float4*)&As[k][ty * 4];
            *(float4*)&av[4] = *(float4*)&As[k][64 + ty * 4];
            *(float4*)&bv[0] = *(float4*)&Bs[k][tx * 4];
            *(float4*)&bv[4] = *(float4*)&Bs[k][64 + tx * 4];
#pragma unroll
            for (int i = 0; i < 8; ++i)
#pragma unroll
                for (int j = 0; j < 8; ++j)
                    acc[i][j] = fmaf(av[i], bv[j], acc[i][j]);
        }
        __syncthreads();
    }

#pragma unroll
    for (int i = 0; i < 8; ++i) {
        const int row = m0 + ((i < 4) ? (ty * 4 + i) : (64 + ty * 4 + (i - 4)));
#pragma unroll
        for (int jh = 0; jh < 2; ++jh) {
            const int col = n0 + jh * 64 + tx * 4;
            float4 v;
            v.x = acc[i][jh * 4 + 0];
            v.y = acc[i][jh * 4 + 1];
            v.z = acc[i][jh * 4 + 2];
            v.w = acc[i][jh * 4 + 3];
            if (BIAS) {
                v.x += bias[col + 0];
                v.y += bias[col + 1];
                v.z += bias[col + 2];
                v.w += bias[col + 3];
            }
            *(float4*)(C + (size_t)row * N + col) = v;
        }
    }
}

// ---------------------------------------------------------------------------
// Flash attention: one block per (query-tile of 64, head, batch).
// 256 threads; thread (ty,tx) owns 4 query rows x 4 cols. Online softmax.
// Q/K/V read from g_qkv (q at col h*64+d, k at +512, v at +1024).
// ---------------------------------------------------------------------------
#define SMS 68   // smem row stride (floats); 68*4B keeps float4 alignment

__global__ __launch_bounds__(256) void attn_kernel(const float* __restrict__ qkv,
                                                   float* __restrict__ ao)
{
    extern __shared__ float sm[];
    float* Qs = sm;                // [64][SMS]  row=query, col=d
    float* Kt = sm + 64 * SMS;     // [64][SMS]  row=d,     col=key   (transposed)
    float* Vs = sm + 2 * 64 * SMS; // [64][SMS]  row=key,   col=d
    float* Ps = sm + 3 * 64 * SMS; // [64][SMS]  row=query, col=key

    const int qt = blockIdx.x, h = blockIdx.y, b = blockIdx.z;
    const int tid = threadIdx.x;
    const int ty = tid >> 4, tx = tid & 15;
    const float scale = 0.125f;   // 1/sqrt(64)

    const float* base = qkv + (size_t)b * NSEQ * QKVC;

    // Load Q tile [64 x 64]
    {
        const int row = tid >> 2, f0 = tid & 3;
        const float* src = base + (size_t)(qt * 64 + row) * QKVC + h * DHEAD;
#pragma unroll
        for (int i = 0; i < 4; ++i) {
            const int d = (f0 + 4 * i) * 4;
            *(float4*)&Qs[row * SMS + d] = *(const float4*)(src + d);
        }
    }

    float m[4], l[4], o[4][4];
#pragma unroll
    for (int r = 0; r < 4; ++r) {
        m[r] = -1e30f;
        l[r] = 0.f;
#pragma unroll
        for (int c = 0; c < 4; ++c) o[r][c] = 0.f;
    }

    for (int jt = 0; jt < NSEQ / 64; ++jt) {
        __syncthreads();   // previous PV done reading Ps/Vs
        // Load K (transposed -> Kt[d][key]) and V tiles
        {
            const int row = tid >> 2, f0 = tid & 3;   // row = key index in tile
            const float* ksrc = base + (size_t)(jt * 64 + row) * QKVC + DIMM + h * DHEAD;
            const float* vsrc = ksrc + DIMM;
#pragma unroll
            for (int i = 0; i < 4; ++i) {
                const int d = (f0 + 4 * i) * 4;
                float4 kv = *(const float4*)(ksrc + d);
                Kt[(d + 0) * SMS + row] = kv.x;
                Kt[(d + 1) * SMS + row] = kv.y;
                Kt[(d + 2) * SMS + row] = kv.z;
                Kt[(d + 3) * SMS + row] = kv.w;
                *(float4*)&Vs[row * SMS + d] = *(const float4*)(vsrc + d);
            }
        }
        __syncthreads();

        // S = Q @ K^T  (thread: 4 rows x 4 key-cols)
        float s[4][4] = {};
#pragma unroll 4
        for (int d = 0; d < 64; d += 4) {
            float4 q4[4], k4[4];
#pragma unroll
            for (int r = 0; r < 4; ++r) q4[r] = *(float4*)&Qs[(ty * 4 + r) * SMS + d];
#pragma unroll
            for (int j = 0; j < 4; ++j) k4[j] = *(float4*)&Kt[(d + j) * SMS + tx * 4];
#pragma unroll
            for (int r = 0; r < 4; ++r) {
                s[r][0] += q4[r].x * k4[0].x + q4[r].y * k4[1].x + q4[r].z * k4[2].x + q4[r].w * k4[3].x;
                s[r][1] += q4[r].x * k4[0].y + q4[r].y * k4[1].y + q4[r].z * k4[2].y + q4[r].w * k4[3].y;
                s[r][2] += q4[r].x * k4[0].z + q4[r].y * k4[1].z + q4[r].z * k4[2].z + q4[r].w * k4[3].z;
                s[r][3] += q4[r].x * k4[0].w + q4[r].y * k4[1].w + q4[r].z * k4[2].w + q4[r].w * k4[3].w;
            }
        }

        // Online softmax update per owned row
#pragma unroll
        for (int r = 0; r < 4; ++r) {
#pragma unroll
            for (int c = 0; c < 4; ++c) s[r][c] *= scale;
            float rm = fmaxf(fmaxf(s[r][0], s[r][1]), fmaxf(s[r][2], s[r][3]));
#pragma unroll
            for (int off = 8; off >= 1; off >>= 1)
                rm = fmaxf(rm, __shfl_xor_sync(0xffffffffu, rm, off));
            const float mn = fmaxf(m[r], rm);
            const float alpha = __expf(m[r] - mn);
            float p0 = __expf(s[r][0] - mn);
            float p1 = __expf(s[r][1] - mn);
            float p2 = __expf(s[r][2] - mn);
            float p3 = __expf(s[r][3] - mn);
            float rs = p0 + p1 + p2 + p3;
#pragma unroll
            for (int off = 8; off >= 1; off >>= 1)
                rs += __shfl_xor_sync(0xffffffffu, rs, off);
            l[r] = l[r] * alpha + rs;
            m[r] = mn;
#pragma unroll
            for (int c = 0; c < 4; ++c) o[r][c] *= alpha;
            *(float4*)&Ps[(ty * 4 + r) * SMS + tx * 4] = make_float4(p0, p1, p2, p3);
        }
        __syncthreads();

        // O += P @ V  (thread: 4 rows x 4 dim-cols)
#pragma unroll 4
        for (int k = 0; k < 64; k += 4) {
            float4 p4[4], v4[4];
#pragma unroll
            for (int r = 0; r < 4; ++r) p4[r] = *(float4*)&Ps[(ty * 4 + r) * SMS + k];
#pragma unroll
            for (int j = 0; j < 4; ++j) v4[j] = *(float4*)&Vs[(k + j) * SMS + tx * 4];
#pragma unroll
            for (int r = 0; r < 4; ++r) {
                o[r][0] += p4[r].x * v4[0].x + p4[r].y * v4[1].x + p4[r].z * v4[2].x + p4[r].w * v4[3].x;
                o[r][1] += p4[r].x * v4[0].y + p4[r].y * v4[1].y + p4[r].z * v4[2].y + p4[r].w * v4[3].y;
                o[r][2] += p4[r].x * v4[0].z + p4[r].y * v4[1].z + p4[r].z * v4[2].z + p4[r].w * v4[3].z;
                o[r][3] += p4[r].x * v4[0].w + p4[r].y * v4[1].w + p4[r].z * v4[2].w + p4[r].w * v4[3].w;
            }
        }
    }

    // Normalize and store to attention-output buffer [b, n, h*64+d]
    float* dst = ao + ((size_t)b * NSEQ + qt * 64) * DIMM + h * DHEAD;
#pragma unroll
    for (int r = 0; r < 4; ++r) {
        const float inv = 1.f / l[r];
        float4 v = make_float4(o[r][0] * inv, o[r][1] * inv, o[r][2] * inv, o[r][3] * inv);
        *(float4*)(dst + (size_t)(ty * 4 + r) * DIMM + tx * 4) = v;
    }
}

// ---------------------------------------------------------------------------
extern "C" void kernel_launch(void* const* d_in, const int* in_sizes, int n_in,
                              void* d_out, int out_size)
{
    const float* x     = (const float*)d_in[0];   // [4, 2048, 512]
    const float* w_qkv = (const float*)d_in[1];   // [512, 1536]
    const float* w_out = (const float*)d_in[2];   // [512, 512]
    const float* b_out = (const float*)d_in[3];   // [512]
    float* out = (float*)d_out;                   // [4, 2048, 512]

    float *qkv, *ao;
    cudaGetSymbolAddress((void**)&qkv, g_qkv);
    cudaGetSymbolAddress((void**)&ao, g_ao);

    const int M = NB * NSEQ;   // 8192

    // 1) QKV projection: [8192,512] @ [512,1536] -> [8192,1536]
    gemm128<false><<<dim3(QKVC / 128, M / 128), 256>>>(x, w_qkv, nullptr, qkv, M, QKVC, DIMM);

    // 2) Flash attention per (query-tile, head, batch)
    const int smem = 4 * 64 * SMS * (int)sizeof(float);   // ~70 KB
    cudaFuncSetAttribute(attn_kernel, cudaFuncAttributeMaxDynamicSharedMemorySize, smem);
    attn_kernel<<<dim3(NSEQ / 64, NH, NB), 256, smem>>>(qkv, ao);

    // 3) Output projection + bias: [8192,512] @ [512,512] + b -> out
    gemm128<true><<<dim3(DIMM / 128, M / 128), 256>>>(ao, w_out, b_out, out, M, DIMM, DIMM);
}

// round 5
// speedup vs baseline: 1.5814x; 1.5814x over previous
#include <cuda_runtime.h>
#include <cuda_bf16.h>
#include <cstdint>
#include <cstddef>

// ---------------------------------------------------------------------------
// Problem constants
// ---------------------------------------------------------------------------
#define NB    4
#define NSEQ  2048
#define DIMM  512
#define NH    8
#define DHEAD 64
#define QKVC  1536   // 3 * inner

// Scratch (no cudaMalloc allowed)
__device__ float g_qkv[(size_t)NB * NSEQ * QKVC];
__device__ float g_ao [(size_t)NB * NSEQ * DIMM];
__device__ __nv_bfloat16 g_wqkvT_hi[(size_t)QKVC * DIMM];
__device__ __nv_bfloat16 g_wqkvT_lo[(size_t)QKVC * DIMM];
__device__ __nv_bfloat16 g_woutT_hi[(size_t)DIMM * DIMM];
__device__ __nv_bfloat16 g_woutT_lo[(size_t)DIMM * DIMM];

// ---------------------------------------------------------------------------
// Helpers
// ---------------------------------------------------------------------------
// split (a,b) into bf16 hi pair + bf16 lo (residual) pair, packed as u32
__device__ __forceinline__ void split_pack(float a, float b, uint32_t& hi, uint32_t& lo) {
    __nv_bfloat162 h = __floats2bfloat162_rn(a, b);
    float ra = a - __bfloat162float(h.x);
    float rb = b - __bfloat162float(h.y);
    __nv_bfloat162 l = __floats2bfloat162_rn(ra, rb);
    hi = reinterpret_cast<uint32_t&>(h);
    lo = reinterpret_cast<uint32_t&>(l);
}

// bf16 MMA: D(16x8) += A(16x16) * B^T, row.col
__device__ __forceinline__ void mma16(float* c, const uint32_t* a, const uint32_t* b) {
    asm volatile(
        "mma.sync.aligned.m16n8k16.row.col.f32.bf16.bf16.f32 "
        "{%0,%1,%2,%3}, {%4,%5,%6,%7}, {%8,%9}, {%0,%1,%2,%3};\n"
        : "+f"(c[0]), "+f"(c[1]), "+f"(c[2]), "+f"(c[3])
        : "r"(a[0]), "r"(a[1]), "r"(a[2]), "r"(a[3]), "r"(b[0]), "r"(b[1]));
}

// ldmatrix x4: A-style tile order (r0: rows0-7/c0, r1: rows8-15/c0, r2: rows0-7/c+16B, r3: rows8-15/c+16B)
__device__ __forceinline__ void ldsmA(uint32_t* f, uint32_t base, int strideB) {
    const int lane = threadIdx.x & 31;
    uint32_t a = base + (uint32_t)((((lane >> 3) & 1) * 8 + (lane & 7)) * strideB + (lane >> 4) * 16);
    asm volatile("ldmatrix.sync.aligned.m8n8.x4.shared.b16 {%0,%1,%2,%3}, [%4];"
                 : "=r"(f[0]), "=r"(f[1]), "=r"(f[2]), "=r"(f[3]) : "r"(a));
}
// trans variant, same tile order (for V^T frags)
__device__ __forceinline__ void ldsmAT(uint32_t* f, uint32_t base, int strideB) {
    const int lane = threadIdx.x & 31;
    uint32_t a = base + (uint32_t)((((lane >> 3) & 1) * 8 + (lane & 7)) * strideB + (lane >> 4) * 16);
    asm volatile("ldmatrix.sync.aligned.m8n8.x4.trans.shared.b16 {%0,%1,%2,%3}, [%4];"
                 : "=r"(f[0]), "=r"(f[1]), "=r"(f[2]), "=r"(f[3]) : "r"(a));
}
// B-style tile order (r0: rows0-7/c0, r1: rows0-7/c+16B, r2: rows8-15/c0, r3: rows8-15/c+16B)
__device__ __forceinline__ void ldsmB(uint32_t* f, uint32_t base, int strideB) {
    const int lane = threadIdx.x & 31;
    uint32_t a = base + (uint32_t)(((lane >> 4) * 8 + (lane & 7)) * strideB + ((lane >> 3) & 1) * 16);
    asm volatile("ldmatrix.sync.aligned.m8n8.x4.shared.b16 {%0,%1,%2,%3}, [%4];"
                 : "=r"(f[0]), "=r"(f[1]), "=r"(f[2]), "=r"(f[3]) : "r"(a));
}

// ---------------------------------------------------------------------------
// Pre-pass: W [K, N] -> transposed hi/lo bf16 planes [N, K]
// ---------------------------------------------------------------------------
__global__ void transpose_split(const float* __restrict__ W,
                                __nv_bfloat16* __restrict__ Thi,
                                __nv_bfloat16* __restrict__ Tlo, int K, int N)
{
    __shared__ float t[32][33];
    const int n0 = blockIdx.x * 32, k0 = blockIdx.y * 32;
    const int tx = threadIdx.x, ty = threadIdx.y;
#pragma unroll
    for (int j = ty; j < 32; j += 8)
        t[j][tx] = W[(size_t)(k0 + j) * N + n0 + tx];
    __syncthreads();
#pragma unroll
    for (int j = ty; j < 32; j += 8) {
        float v = t[tx][j];
        __nv_bfloat16 h = __float2bfloat16(v);
        Thi[(size_t)(n0 + j) * K + k0 + tx] = h;
        Tlo[(size_t)(n0 + j) * K + k0 + tx] = __float2bfloat16(v - __bfloat162float(h));
    }
}

// ---------------------------------------------------------------------------
// bf16x3 GEMM: C[M,N] = A[M,K] @ BT[N,K]^T (+bias)
// A fp32 (split in loader); BT pre-split hi/lo planes.
// 128x128 CTA tile, BK=32, 8 warps (2x4), warp tile 64x32. Double-buffered.
// ---------------------------------------------------------------------------
#define GP 40                 // gemm smem row stride (bf16)
#define GPLANE (128 * GP)     // bf16 elems per plane

template <bool BIAS>
__global__ __launch_bounds__(256)
void gemm_bf16x3(const float* __restrict__ A,
                 const __nv_bfloat16* __restrict__ Bh,
                 const __nv_bfloat16* __restrict__ Bl,
                 const float* __restrict__ bias, float* __restrict__ C,
                 int M, int N, int K)
{
    extern __shared__ __nv_bfloat16 smg[];
    // per buffer: Ahi, Alo, Bhi, Blo planes
    const int tid = threadIdx.x;
    const int wid = tid >> 5, lane = tid & 31;
    const int gid = lane >> 2, tig = lane & 3;
    const int wm = wid >> 2, wn = wid & 3;
    const int m0 = blockIdx.y * 128, n0 = blockIdx.x * 128;
    const int lr = tid >> 3, lf = tid & 7;
    const int NC = K >> 5;

    const uint32_t smg_u = (uint32_t)__cvta_generic_to_shared(smg);

    float4 ar[4];
    uint2 brh[4], brl[4];

    auto fetch = [&](int c) {
        const int kc = c * 32 + lf * 4;
#pragma unroll
        for (int p = 0; p < 4; ++p) {
            const int row = lr + p * 32;
            ar[p] = *(const float4*)(A + (size_t)(m0 + row) * K + kc);
            brh[p] = *(const uint2*)(Bh + (size_t)(n0 + row) * K + kc);
            brl[p] = *(const uint2*)(Bl + (size_t)(n0 + row) * K + kc);
        }
    };
    auto stor = [&](int bb) {
        __nv_bfloat16* base = smg + bb * 4 * GPLANE;
#pragma unroll
        for (int p = 0; p < 4; ++p) {
            const int row = lr + p * 32;
            const int ofs = row * GP + lf * 4;
            uint32_t h0, l0, h1, l1;
            split_pack(ar[p].x, ar[p].y, h0, l0);
            split_pack(ar[p].z, ar[p].w, h1, l1);
            *(uint2*)(base + ofs) = make_uint2(h0, h1);                 // Ahi
            *(uint2*)(base + GPLANE + ofs) = make_uint2(l0, l1);        // Alo
            *(uint2*)(base + 2 * GPLANE + ofs) = brh[p];                // Bhi
            *(uint2*)(base + 3 * GPLANE + ofs) = brl[p];                // Blo
        }
    };

    float acc[4][4][4] = {};

    fetch(0); stor(0); __syncthreads();

    for (int c = 0; c < NC; ++c) {
        if (c + 1 < NC) fetch(c + 1);
        const uint32_t bu = smg_u + (uint32_t)((c & 1) * 4 * GPLANE) * 2;
        const uint32_t Ahi_u = bu, Alo_u = bu + GPLANE * 2;
        const uint32_t Bhi_u = bu + 2 * GPLANE * 2, Blo_u = bu + 3 * GPLANE * 2;
#pragma unroll
        for (int ks = 0; ks < 2; ++ks) {
            uint32_t ah[4][4], al[4][4];
#pragma unroll
            for (int i = 0; i < 4; ++i) {
                const uint32_t ro = (uint32_t)(((wm * 64 + i * 16) * GP + ks * 16) * 2);
                ldsmA(ah[i], Ahi_u + ro, GP * 2);
                ldsmA(al[i], Alo_u + ro, GP * 2);
            }
            uint32_t bh2[4][2], bl2[4][2];
#pragma unroll
            for (int nb = 0; nb < 2; ++nb) {
                const uint32_t ro = (uint32_t)(((wn * 32 + nb * 16) * GP + ks * 16) * 2);
                uint32_t t[4];
                ldsmB(t, Bhi_u + ro, GP * 2);
                bh2[nb * 2][0] = t[0]; bh2[nb * 2][1] = t[1];
                bh2[nb * 2 + 1][0] = t[2]; bh2[nb * 2 + 1][1] = t[3];
                ldsmB(t, Blo_u + ro, GP * 2);
                bl2[nb * 2][0] = t[0]; bl2[nb * 2][1] = t[1];
                bl2[nb * 2 + 1][0] = t[2]; bl2[nb * 2 + 1][1] = t[3];
            }
#pragma unroll
            for (int i = 0; i < 4; ++i)
#pragma unroll
                for (int j = 0; j < 4; ++j) {
                    mma16(acc[i][j], ah[i], bh2[j]);
                    mma16(acc[i][j], ah[i], bl2[j]);
                    mma16(acc[i][j], al[i], bh2[j]);
                }
        }
        if (c + 1 < NC) { __syncthreads(); stor((c + 1) & 1); __syncthreads(); }
    }

    // epilogue
#pragma unroll
    for (int i = 0; i < 4; ++i) {
        const int r0 = m0 + wm * 64 + i * 16 + gid;
#pragma unroll
        for (int j = 0; j < 4; ++j) {
            const int col = n0 + wn * 32 + j * 8 + tig * 2;
            float bx = 0.f, by = 0.f;
            if (BIAS) { bx = bias[col]; by = bias[col + 1]; }
            float2 v0 = { acc[i][j][0] + bx, acc[i][j][1] + by };
            float2 v1 = { acc[i][j][2] + bx, acc[i][j][3] + by };
            *(float2*)(C + (size_t)r0 * N + col) = v0;
            *(float2*)(C + (size_t)(r0 + 8) * N + col) = v1;
        }
    }
}

// ---------------------------------------------------------------------------
// Flash attention, bf16x3. 256 threads (8 warps), 128 queries per block;
// warp owns 16 query rows. K/V tiles of 64 keys.
// ---------------------------------------------------------------------------
#define AP 72                 // attn smem row stride (bf16)
#define APLANE_Q (128 * AP)
#define APLANE_K (64 * AP)

__global__ __launch_bounds__(256)
void attn_bf16x3(const float* __restrict__ qkv, float* __restrict__ ao)
{
    extern __shared__ __nv_bfloat16 smb[];
    __nv_bfloat16* QPh = smb;                    // Q then P, hi
    __nv_bfloat16* QPl = QPh + APLANE_Q;         // Q then P, lo
    __nv_bfloat16* Kh = QPl + APLANE_Q;
    __nv_bfloat16* Kl = Kh + APLANE_K;
    __nv_bfloat16* Vh = Kl + APLANE_K;
    __nv_bfloat16* Vl = Vh + APLANE_K;

    const uint32_t QPh_u = (uint32_t)__cvta_generic_to_shared(QPh);
    const uint32_t QPl_u = (uint32_t)__cvta_generic_to_shared(QPl);
    const uint32_t Kh_u = (uint32_t)__cvta_generic_to_shared(Kh);
    const uint32_t Kl_u = (uint32_t)__cvta_generic_to_shared(Kl);
    const uint32_t Vh_u = (uint32_t)__cvta_generic_to_shared(Vh);
    const uint32_t Vl_u = (uint32_t)__cvta_generic_to_shared(Vl);

    const int qt = blockIdx.x, h = blockIdx.y, b = blockIdx.z;
    const int tid = threadIdx.x;
    const int wid = tid >> 5, lane = tid & 31;
    const int gid = lane >> 2, tig = lane & 3;
    const int w16 = wid * 16;
    const int lf = tid & 15, lr = tid >> 4;

    const float* base = qkv + (size_t)b * NSEQ * QKVC;

    // Load Q tile [128 x 64], split to bf16 planes
    {
        const float* q0 = base + (size_t)(qt * 128) * QKVC + h * DHEAD;
#pragma unroll
        for (int p = 0; p < 8; ++p) {
            const int row = p * 16 + lr;
            float4 v = *(const float4*)(q0 + (size_t)row * QKVC + lf * 4);
            uint32_t h0, l0, h1, l1;
            split_pack(v.x, v.y, h0, l0);
            split_pack(v.z, v.w, h1, l1);
            *(uint2*)(QPh + row * AP + lf * 4) = make_uint2(h0, h1);
            *(uint2*)(QPl + row * AP + lf * 4) = make_uint2(l0, l1);
        }
    }
    __syncthreads();

    // Q fragments, register-resident
    uint32_t qh[4][4], ql[4][4];
#pragma unroll
    for (int ks = 0; ks < 4; ++ks) {
        const uint32_t ro = (uint32_t)((w16 * AP + ks * 16) * 2);
        ldsmA(qh[ks], QPh_u + ro, AP * 2);
        ldsmA(ql[ks], QPl_u + ro, AP * 2);
    }

    float m0 = -1e30f, m1 = -1e30f, l0 = 0.f, l1 = 0.f;
    float O[8][4] = {};

    for (int jt = 0; jt < NSEQ / 64; ++jt) {
        __syncthreads();   // all warps done with previous K/V
        {
            const float* k0p = base + (size_t)(jt * 64) * QKVC + DIMM + h * DHEAD;
#pragma unroll
            for (int p = 0; p < 4; ++p) {
                const int row = p * 16 + lr;
                const float* kr = k0p + (size_t)row * QKVC;
                float4 kv = *(const float4*)(kr + lf * 4);
                float4 vv = *(const float4*)(kr + DIMM + lf * 4);
                uint32_t h0, lo0, h1, lo1;
                split_pack(kv.x, kv.y, h0, lo0);
                split_pack(kv.z, kv.w, h1, lo1);
                *(uint2*)(Kh + row * AP + lf * 4) = make_uint2(h0, h1);
                *(uint2*)(Kl + row * AP + lf * 4) = make_uint2(lo0, lo1);
                split_pack(vv.x, vv.y, h0, lo0);
                split_pack(vv.z, vv.w, h1, lo1);
                *(uint2*)(Vh + row * AP + lf * 4) = make_uint2(h0, h1);
                *(uint2*)(Vl + row * AP + lf * 4) = make_uint2(lo0, lo1);
            }
        }
        __syncthreads();

        // S = Q @ K^T : warp 16 rows x 64 keys
        float s[8][4];
#pragma unroll
        for (int j = 0; j < 8; ++j) { s[j][0] = s[j][1] = s[j][2] = s[j][3] = 0.f; }
#pragma unroll
        for (int ks = 0; ks < 4; ++ks) {
            uint32_t bh[8][2], bl[8][2];
#pragma unroll
            for (int kb = 0; kb < 4; ++kb) {
                const uint32_t ro = (uint32_t)((kb * 16 * AP + ks * 16) * 2);
                uint32_t t[4];
                ldsmB(t, Kh_u + ro, AP * 2);
                bh[kb * 2][0] = t[0]; bh[kb * 2][1] = t[1];
                bh[kb * 2 + 1][0] = t[2]; bh[kb * 2 + 1][1] = t[3];
                ldsmB(t, Kl_u + ro, AP * 2);
                bl[kb * 2][0] = t[0]; bl[kb * 2][1] = t[1];
                bl[kb * 2 + 1][0] = t[2]; bl[kb * 2 + 1][1] = t[3];
            }
#pragma unroll
            for (int j = 0; j < 8; ++j) {
                mma16(s[j], qh[ks], bh[j]);
                mma16(s[j], qh[ks], bl[j]);
                mma16(s[j], ql[ks], bh[j]);
            }
        }

        // Online softmax (rows gid -> c0,c1; gid+8 -> c2,c3; cols over tig quad)
        float rm0 = -1e30f, rm1 = -1e30f;
#pragma unroll
        for (int j = 0; j < 8; ++j) {
            s[j][0] *= 0.125f; s[j][1] *= 0.125f; s[j][2] *= 0.125f; s[j][3] *= 0.125f;
            rm0 = fmaxf(rm0, fmaxf(s[j][0], s[j][1]));
            rm1 = fmaxf(rm1, fmaxf(s[j][2], s[j][3]));
        }
        rm0 = fmaxf(rm0, __shfl_xor_sync(~0u, rm0, 1));
        rm0 = fmaxf(rm0, __shfl_xor_sync(~0u, rm0, 2));
        rm1 = fmaxf(rm1, __shfl_xor_sync(~0u, rm1, 1));
        rm1 = fmaxf(rm1, __shfl_xor_sync(~0u, rm1, 2));
        const float mn0 = fmaxf(m0, rm0), mn1 = fmaxf(m1, rm1);
        const float a0 = __expf(m0 - mn0), a1 = __expf(m1 - mn1);
        m0 = mn0; m1 = mn1;

        float rs0 = 0.f, rs1 = 0.f;
#pragma unroll
        for (int j = 0; j < 8; ++j) {
            float p0 = __expf(s[j][0] - mn0);
            float p1 = __expf(s[j][1] - mn0);
            float p2 = __expf(s[j][2] - mn1);
            float p3 = __expf(s[j][3] - mn1);
            rs0 += p0 + p1; rs1 += p2 + p3;
            uint32_t hh, ll;
            split_pack(p0, p1, hh, ll);
            *(uint32_t*)(QPh + (w16 + gid) * AP + j * 8 + tig * 2) = hh;
            *(uint32_t*)(QPl + (w16 + gid) * AP + j * 8 + tig * 2) = ll;
            split_pack(p2, p3, hh, ll);
            *(uint32_t*)(QPh + (w16 + gid + 8) * AP + j * 8 + tig * 2) = hh;
            *(uint32_t*)(QPl + (w16 + gid + 8) * AP + j * 8 + tig * 2) = ll;
        }
        rs0 += __shfl_xor_sync(~0u, rs0, 1);
        rs0 += __shfl_xor_sync(~0u, rs0, 2);
        rs1 += __shfl_xor_sync(~0u, rs1, 1);
        rs1 += __shfl_xor_sync(~0u, rs1, 2);
        l0 = l0 * a0 + rs0;
        l1 = l1 * a1 + rs1;
#pragma unroll
        for (int j = 0; j < 8; ++j) {
            O[j][0] *= a0; O[j][1] *= a0; O[j][2] *= a1; O[j][3] *= a1;
        }
        __syncwarp();   // P rows are warp-private (w16..w16+15)

        // O += P @ V (V^T frags via ldmatrix.trans)
#pragma unroll
        for (int ks = 0; ks < 4; ++ks) {
            uint32_t pah[4], pal[4];
            const uint32_t pro = (uint32_t)((w16 * AP + ks * 16) * 2);
            ldsmA(pah, QPh_u + pro, AP * 2);
            ldsmA(pal, QPl_u + pro, AP * 2);
            uint32_t vh[8][2], vl[8][2];
#pragma unroll
            for (int db = 0; db < 4; ++db) {
                const uint32_t ro = (uint32_t)((ks * 16 * AP + db * 16) * 2);
                uint32_t t[4];
                ldsmAT(t, Vh_u + ro, AP * 2);
                vh[db * 2][0] = t[0]; vh[db * 2][1] = t[1];
                vh[db * 2 + 1][0] = t[2]; vh[db * 2 + 1][1] = t[3];
                ldsmAT(t, Vl_u + ro, AP * 2);
                vl[db * 2][0] = t[0]; vl[db * 2][1] = t[1];
                vl[db * 2 + 1][0] = t[2]; vl[db * 2 + 1][1] = t[3];
            }
#pragma unroll
            for (int j = 0; j < 8; ++j) {
                mma16(O[j], pah, vh[j]);
                mma16(O[j], pah, vl[j]);
                mma16(O[j], pal, vh[j]);
            }
        }
    }

    // Epilogue: normalize, store fp32
    const float i0 = 1.f / l0, i1 = 1.f / l1;
    float* d0 = ao + ((size_t)b * NSEQ + qt * 128 + w16 + gid) * DIMM + h * DHEAD;
    float* d1 = d0 + 8 * DIMM;
#pragma unroll
    for (int j = 0; j < 8; ++j) {
        const int col = j * 8 + tig * 2;
        *(float2*)(d0 + col) = make_float2(O[j][0] * i0, O[j][1] * i0);
        *(float2*)(d1 + col) = make_float2(O[j][2] * i1, O[j][3] * i1);
    }
}

// ---------------------------------------------------------------------------
extern "C" void kernel_launch(void* const* d_in, const int* in_sizes, int n_in,
                              void* d_out, int out_size)
{
    const float* x     = (const float*)d_in[0];
    const float* w_qkv = (const float*)d_in[1];
    const float* w_out = (const float*)d_in[2];
    const float* b_out = (const float*)d_in[3];
    float* out = (float*)d_out;

    float *qkv, *ao;
    __nv_bfloat16 *wqh, *wql, *woh, *wol;
    cudaGetSymbolAddress((void**)&qkv, g_qkv);
    cudaGetSymbolAddress((void**)&ao, g_ao);
    cudaGetSymbolAddress((void**)&wqh, g_wqkvT_hi);
    cudaGetSymbolAddress((void**)&wql, g_wqkvT_lo);
    cudaGetSymbolAddress((void**)&woh, g_woutT_hi);
    cudaGetSymbolAddress((void**)&wol, g_woutT_lo);

    const int M = NB * NSEQ;   // 8192

    // 0) transpose + split weights to bf16 hi/lo planes
    transpose_split<<<dim3(QKVC / 32, DIMM / 32), dim3(32, 8)>>>(w_qkv, wqh, wql, DIMM, QKVC);
    transpose_split<<<dim3(DIMM / 32, DIMM / 32), dim3(32, 8)>>>(w_out, woh, wol, DIMM, DIMM);

    // 1) QKV projection
    const int gsmem = 2 * 4 * GPLANE * (int)sizeof(__nv_bfloat16);   // 81920
    cudaFuncSetAttribute(gemm_bf16x3<false>, cudaFuncAttributeMaxDynamicSharedMemorySize, gsmem);
    cudaFuncSetAttribute(gemm_bf16x3<true>,  cudaFuncAttributeMaxDynamicSharedMemorySize, gsmem);
    gemm_bf16x3<false><<<dim3(QKVC / 128, M / 128), 256, gsmem>>>(x, wqh, wql, nullptr, qkv, M, QKVC, DIMM);

    // 2) Flash attention
    const int asmem = (2 * APLANE_Q + 4 * APLANE_K) * (int)sizeof(__nv_bfloat16);   // 73728
    cudaFuncSetAttribute(attn_bf16x3, cudaFuncAttributeMaxDynamicSharedMemorySize, asmem);
    attn_bf16x3<<<dim3(NSEQ / 128, NH, NB), 256, asmem>>>(qkv, ao);

    // 3) Output projection + bias
    gemm_bf16x3<true><<<dim3(DIMM / 128, M / 128), 256, gsmem>>>(ao, woh, wol, b_out, out, M, DIMM, DIMM);
}

// round 6
// speedup vs baseline: 2.5725x; 1.6267x over previous
#include <cuda_runtime.h>
#include <cuda_bf16.h>
#include <cstdint>
#include <cstddef>

// ---------------------------------------------------------------------------
// Problem constants
// ---------------------------------------------------------------------------
#define NB    4
#define NSEQ  2048
#define DIMM  512
#define NH    8
#define DHEAD 64
#define QKVC  1536   // 3 * inner

// Scratch (no cudaMalloc allowed)
__device__ float g_qkv[(size_t)NB * NSEQ * QKVC];
__device__ float g_ao [(size_t)NB * NSEQ * DIMM];
__device__ __nv_bfloat16 g_wqkvT_hi[(size_t)QKVC * DIMM];
__device__ __nv_bfloat16 g_wqkvT_lo[(size_t)QKVC * DIMM];
__device__ __nv_bfloat16 g_woutT_hi[(size_t)DIMM * DIMM];
__device__ __nv_bfloat16 g_woutT_lo[(size_t)DIMM * DIMM];

// ---------------------------------------------------------------------------
// Helpers
// ---------------------------------------------------------------------------
__device__ __forceinline__ void split_pack(float a, float b, uint32_t& hi, uint32_t& lo) {
    __nv_bfloat162 h = __floats2bfloat162_rn(a, b);
    float ra = a - __bfloat162float(h.x);
    float rb = b - __bfloat162float(h.y);
    __nv_bfloat162 l = __floats2bfloat162_rn(ra, rb);
    hi = reinterpret_cast<uint32_t&>(h);
    lo = reinterpret_cast<uint32_t&>(l);
}

__device__ __forceinline__ void mma16(float* c, const uint32_t* a, const uint32_t* b) {
    asm volatile(
        "mma.sync.aligned.m16n8k16.row.col.f32.bf16.bf16.f32 "
        "{%0,%1,%2,%3}, {%4,%5,%6,%7}, {%8,%9}, {%0,%1,%2,%3};\n"
        : "+f"(c[0]), "+f"(c[1]), "+f"(c[2]), "+f"(c[3])
        : "r"(a[0]), "r"(a[1]), "r"(a[2]), "r"(a[3]), "r"(b[0]), "r"(b[1]));
}

// ldmatrix x4, A-style tile order
__device__ __forceinline__ void ldsmA(uint32_t* f, uint32_t base, int strideB) {
    const int lane = threadIdx.x & 31;
    uint32_t a = base + (uint32_t)((((lane >> 3) & 1) * 8 + (lane & 7)) * strideB + (lane >> 4) * 16);
    asm volatile("ldmatrix.sync.aligned.m8n8.x4.shared.b16 {%0,%1,%2,%3}, [%4];"
                 : "=r"(f[0]), "=r"(f[1]), "=r"(f[2]), "=r"(f[3]) : "r"(a));
}
__device__ __forceinline__ void ldsmAT(uint32_t* f, uint32_t base, int strideB) {
    const int lane = threadIdx.x & 31;
    uint32_t a = base + (uint32_t)((((lane >> 3) & 1) * 8 + (lane & 7)) * strideB + (lane >> 4) * 16);
    asm volatile("ldmatrix.sync.aligned.m8n8.x4.trans.shared.b16 {%0,%1,%2,%3}, [%4];"
                 : "=r"(f[0]), "=r"(f[1]), "=r"(f[2]), "=r"(f[3]) : "r"(a));
}
__device__ __forceinline__ void ldsmB(uint32_t* f, uint32_t base, int strideB) {
    const int lane = threadIdx.x & 31;
    uint32_t a = base + (uint32_t)(((lane >> 4) * 8 + (lane & 7)) * strideB + ((lane >> 3) & 1) * 16);
    asm volatile("ldmatrix.sync.aligned.m8n8.x4.shared.b16 {%0,%1,%2,%3}, [%4];"
                 : "=r"(f[0]), "=r"(f[1]), "=r"(f[2]), "=r"(f[3]) : "r"(a));
}

// ---------------------------------------------------------------------------
// Pre-pass: W [K, N] -> transposed hi/lo bf16 planes [N, K]
// ---------------------------------------------------------------------------
__global__ void transpose_split(const float* __restrict__ W,
                                __nv_bfloat16* __restrict__ Thi,
                                __nv_bfloat16* __restrict__ Tlo, int K, int N)
{
    __shared__ float t[32][33];
    const int n0 = blockIdx.x * 32, k0 = blockIdx.y * 32;
    const int tx = threadIdx.x, ty = threadIdx.y;
#pragma unroll
    for (int j = ty; j < 32; j += 8)
        t[j][tx] = W[(size_t)(k0 + j) * N + n0 + tx];
    __syncthreads();
#pragma unroll
    for (int j = ty; j < 32; j += 8) {
        float v = t[tx][j];
        __nv_bfloat16 h = __float2bfloat16(v);
        Thi[(size_t)(n0 + j) * K + k0 + tx] = h;
        Tlo[(size_t)(n0 + j) * K + k0 + tx] = __float2bfloat16(v - __bfloat162float(h));
    }
}

// ---------------------------------------------------------------------------
// bf16x3 GEMM: C[M,N] = A[M,K] @ BT[N,K]^T (+bias)
// ---------------------------------------------------------------------------
#define GP 40
#define GPLANE (128 * GP)

template <bool BIAS>
__global__ __launch_bounds__(256)
void gemm_bf16x3(const float* __restrict__ A,
                 const __nv_bfloat16* __restrict__ Bh,
                 const __nv_bfloat16* __restrict__ Bl,
                 const float* __restrict__ bias, float* __restrict__ C,
                 int M, int N, int K)
{
    extern __shared__ __nv_bfloat16 smg[];
    const int tid = threadIdx.x;
    const int wid = tid >> 5, lane = tid & 31;
    const int gid = lane >> 2, tig = lane & 3;
    const int wm = wid >> 2, wn = wid & 3;
    const int m0 = blockIdx.y * 128, n0 = blockIdx.x * 128;
    const int lr = tid >> 3, lf = tid & 7;
    const int NC = K >> 5;

    const uint32_t smg_u = (uint32_t)__cvta_generic_to_shared(smg);

    float4 ar[4];
    uint2 brh[4], brl[4];

    auto fetch = [&](int c) {
        const int kc = c * 32 + lf * 4;
#pragma unroll
        for (int p = 0; p < 4; ++p) {
            const int row = lr + p * 32;
            ar[p] = *(const float4*)(A + (size_t)(m0 + row) * K + kc);
            brh[p] = *(const uint2*)(Bh + (size_t)(n0 + row) * K + kc);
            brl[p] = *(const uint2*)(Bl + (size_t)(n0 + row) * K + kc);
        }
    };
    auto stor = [&](int bb) {
        __nv_bfloat16* base = smg + bb * 4 * GPLANE;
#pragma unroll
        for (int p = 0; p < 4; ++p) {
            const int row = lr + p * 32;
            const int ofs = row * GP + lf * 4;
            uint32_t h0, l0, h1, l1;
            split_pack(ar[p].x, ar[p].y, h0, l0);
            split_pack(ar[p].z, ar[p].w, h1, l1);
            *(uint2*)(base + ofs) = make_uint2(h0, h1);
            *(uint2*)(base + GPLANE + ofs) = make_uint2(l0, l1);
            *(uint2*)(base + 2 * GPLANE + ofs) = brh[p];
            *(uint2*)(base + 3 * GPLANE + ofs) = brl[p];
        }
    };

    float acc[4][4][4] = {};

    fetch(0); stor(0); __syncthreads();

    for (int c = 0; c < NC; ++c) {
        if (c + 1 < NC) fetch(c + 1);
        const uint32_t bu = smg_u + (uint32_t)((c & 1) * 4 * GPLANE) * 2;
        const uint32_t Ahi_u = bu, Alo_u = bu + GPLANE * 2;
        const uint32_t Bhi_u = bu + 2 * GPLANE * 2, Blo_u = bu + 3 * GPLANE * 2;
#pragma unroll
        for (int ks = 0; ks < 2; ++ks) {
            uint32_t ah[4][4], al[4][4];
#pragma unroll
            for (int i = 0; i < 4; ++i) {
                const uint32_t ro = (uint32_t)(((wm * 64 + i * 16) * GP + ks * 16) * 2);
                ldsmA(ah[i], Ahi_u + ro, GP * 2);
                ldsmA(al[i], Alo_u + ro, GP * 2);
            }
            uint32_t bh2[4][2], bl2[4][2];
#pragma unroll
            for (int nb = 0; nb < 2; ++nb) {
                const uint32_t ro = (uint32_t)(((wn * 32 + nb * 16) * GP + ks * 16) * 2);
                uint32_t t[4];
                ldsmB(t, Bhi_u + ro, GP * 2);
                bh2[nb * 2][0] = t[0]; bh2[nb * 2][1] = t[1];
                bh2[nb * 2 + 1][0] = t[2]; bh2[nb * 2 + 1][1] = t[3];
                ldsmB(t, Blo_u + ro, GP * 2);
                bl2[nb * 2][0] = t[0]; bl2[nb * 2][1] = t[1];
                bl2[nb * 2 + 1][0] = t[2]; bl2[nb * 2 + 1][1] = t[3];
            }
#pragma unroll
            for (int i = 0; i < 4; ++i)
#pragma unroll
                for (int j = 0; j < 4; ++j) {
                    mma16(acc[i][j], ah[i], bh2[j]);
                    mma16(acc[i][j], ah[i], bl2[j]);
                    mma16(acc[i][j], al[i], bh2[j]);
                }
        }
        // single sync: target buffer (c+1)&1 was last read before the previous
        // iteration-boundary sync, so writing it is race-free now.
        if (c + 1 < NC) { stor((c + 1) & 1); __syncthreads(); }
    }

#pragma unroll
    for (int i = 0; i < 4; ++i) {
        const int r0 = m0 + wm * 64 + i * 16 + gid;
#pragma unroll
        for (int j = 0; j < 4; ++j) {
            const int col = n0 + wn * 32 + j * 8 + tig * 2;
            float bx = 0.f, by = 0.f;
            if (BIAS) { bx = bias[col]; by = bias[col + 1]; }
            float2 v0 = { acc[i][j][0] + bx, acc[i][j][1] + by };
            float2 v1 = { acc[i][j][2] + bx, acc[i][j][3] + by };
            *(float2*)(C + (size_t)r0 * N + col) = v0;
            *(float2*)(C + (size_t)(r0 + 8) * N + col) = v1;
        }
    }
}

// ---------------------------------------------------------------------------
// Flash attention, bf16x3, software-pipelined K/V (double-buffered smem +
// register prefetch). 256 threads, 128 queries per block, K-tiles of 64.
// ---------------------------------------------------------------------------
#define AP 72
#define APLANE_Q (128 * AP)
#define APLANE_K (64 * AP)
#define KVBUF (4 * APLANE_K)   // Kh, Kl, Vh, Vl planes per buffer

__global__ __launch_bounds__(256)
void attn_bf16x3(const float* __restrict__ qkv, float* __restrict__ ao)
{
    extern __shared__ __nv_bfloat16 smb[];
    __nv_bfloat16* QPh = smb;
    __nv_bfloat16* QPl = QPh + APLANE_Q;
    __nv_bfloat16* KV  = QPl + APLANE_Q;   // [2][4 planes][64][AP]

    const uint32_t QPh_u = (uint32_t)__cvta_generic_to_shared(QPh);
    const uint32_t QPl_u = (uint32_t)__cvta_generic_to_shared(QPl);
    const uint32_t KV_u  = (uint32_t)__cvta_generic_to_shared(KV);

    const int qt = blockIdx.x, h = blockIdx.y, b = blockIdx.z;
    const int tid = threadIdx.x;
    const int wid = tid >> 5, lane = tid & 31;
    const int gid = lane >> 2, tig = lane & 3;
    const int w16 = wid * 16;
    const int lf = tid & 15, lr = tid >> 4;

    const float* base = qkv + (size_t)b * NSEQ * QKVC;

    // Load Q tile [128 x 64], split to bf16 planes
    {
        const float* q0 = base + (size_t)(qt * 128) * QKVC + h * DHEAD;
#pragma unroll
        for (int p = 0; p < 8; ++p) {
            const int row = p * 16 + lr;
            float4 v = *(const float4*)(q0 + (size_t)row * QKVC + lf * 4);
            uint32_t h0, l0, h1, l1;
            split_pack(v.x, v.y, h0, l0);
            split_pack(v.z, v.w, h1, l1);
            *(uint2*)(QPh + row * AP + lf * 4) = make_uint2(h0, h1);
            *(uint2*)(QPl + row * AP + lf * 4) = make_uint2(l0, l1);
        }
    }

    // K/V prefetch registers (4 rows each of K and V as float4)
    float4 kfr[4], vfr[4];
    auto fetchKV = [&](int jt) {
        const float* k0p = base + (size_t)(jt * 64) * QKVC + DIMM + h * DHEAD;
#pragma unroll
        for (int p = 0; p < 4; ++p) {
            const float* kr = k0p + (size_t)(p * 16 + lr) * QKVC;
            kfr[p] = *(const float4*)(kr + lf * 4);
            vfr[p] = *(const float4*)(kr + DIMM + lf * 4);
        }
    };
    auto storKV = [&](int bb) {
        __nv_bfloat16* Bb = KV + bb * KVBUF;
#pragma unroll
        for (int p = 0; p < 4; ++p) {
            const int ofs = (p * 16 + lr) * AP + lf * 4;
            uint32_t h0, lo0, h1, lo1;
            split_pack(kfr[p].x, kfr[p].y, h0, lo0);
            split_pack(kfr[p].z, kfr[p].w, h1, lo1);
            *(uint2*)(Bb + ofs) = make_uint2(h0, h1);                        // Kh
            *(uint2*)(Bb + APLANE_K + ofs) = make_uint2(lo0, lo1);           // Kl
            split_pack(vfr[p].x, vfr[p].y, h0, lo0);
            split_pack(vfr[p].z, vfr[p].w, h1, lo1);
            *(uint2*)(Bb + 2 * APLANE_K + ofs) = make_uint2(h0, h1);         // Vh
            *(uint2*)(Bb + 3 * APLANE_K + ofs) = make_uint2(lo0, lo1);       // Vl
        }
    };

    fetchKV(0);
    storKV(0);
    __syncthreads();   // Q planes + KV buf0 visible

    // Q fragments, register-resident
    uint32_t qh[4][4], ql[4][4];
#pragma unroll
    for (int ks = 0; ks < 4; ++ks) {
        const uint32_t ro = (uint32_t)((w16 * AP + ks * 16) * 2);
        ldsmA(qh[ks], QPh_u + ro, AP * 2);
        ldsmA(ql[ks], QPl_u + ro, AP * 2);
    }

    float m0 = -1e30f, m1 = -1e30f, l0 = 0.f, l1 = 0.f;
    float O[8][4] = {};

    const int NT = NSEQ / 64;
    for (int jt = 0; jt < NT; ++jt) {
        // issue next tile's global loads; they complete during the mma stream
        if (jt + 1 < NT) fetchKV(jt + 1);

        const uint32_t bu = KV_u + (uint32_t)((jt & 1) * KVBUF) * 2;
        const uint32_t Kh_u = bu, Kl_u = bu + APLANE_K * 2;
        const uint32_t Vh_u = bu + 2 * APLANE_K * 2, Vl_u = bu + 3 * APLANE_K * 2;

        // S = Q @ K^T : warp 16 rows x 64 keys
        float s[8][4];
#pragma unroll
        for (int j = 0; j < 8; ++j) { s[j][0] = s[j][1] = s[j][2] = s[j][3] = 0.f; }
#pragma unroll
        for (int ks = 0; ks < 4; ++ks) {
            uint32_t bh[8][2], bl[8][2];
#pragma unroll
            for (int kb = 0; kb < 4; ++kb) {
                const uint32_t ro = (uint32_t)((kb * 16 * AP + ks * 16) * 2);
                uint32_t t[4];
                ldsmB(t, Kh_u + ro, AP * 2);
                bh[kb * 2][0] = t[0]; bh[kb * 2][1] = t[1];
                bh[kb * 2 + 1][0] = t[2]; bh[kb * 2 + 1][1] = t[3];
                ldsmB(t, Kl_u + ro, AP * 2);
                bl[kb * 2][0] = t[0]; bl[kb * 2][1] = t[1];
                bl[kb * 2 + 1][0] = t[2]; bl[kb * 2 + 1][1] = t[3];
            }
#pragma unroll
            for (int j = 0; j < 8; ++j) {
                mma16(s[j], qh[ks], bh[j]);
                mma16(s[j], qh[ks], bl[j]);
                mma16(s[j], ql[ks], bh[j]);
            }
        }

        // Online softmax
        float rm0 = -1e30f, rm1 = -1e30f;
#pragma unroll
        for (int j = 0; j < 8; ++j) {
            s[j][0] *= 0.125f; s[j][1] *= 0.125f; s[j][2] *= 0.125f; s[j][3] *= 0.125f;
            rm0 = fmaxf(rm0, fmaxf(s[j][0], s[j][1]));
            rm1 = fmaxf(rm1, fmaxf(s[j][2], s[j][3]));
        }
        rm0 = fmaxf(rm0, __shfl_xor_sync(~0u, rm0, 1));
        rm0 = fmaxf(rm0, __shfl_xor_sync(~0u, rm0, 2));
        rm1 = fmaxf(rm1, __shfl_xor_sync(~0u, rm1, 1));
        rm1 = fmaxf(rm1, __shfl_xor_sync(~0u, rm1, 2));
        const float mn0 = fmaxf(m0, rm0), mn1 = fmaxf(m1, rm1);
        const float a0 = __expf(m0 - mn0), a1 = __expf(m1 - mn1);
        m0 = mn0; m1 = mn1;

        float rs0 = 0.f, rs1 = 0.f;
#pragma unroll
        for (int j = 0; j < 8; ++j) {
            float p0 = __expf(s[j][0] - mn0);
            float p1 = __expf(s[j][1] - mn0);
            float p2 = __expf(s[j][2] - mn1);
            float p3 = __expf(s[j][3] - mn1);
            rs0 += p0 + p1; rs1 += p2 + p3;
            uint32_t hh, ll;
            split_pack(p0, p1, hh, ll);
            *(uint32_t*)(QPh + (w16 + gid) * AP + j * 8 + tig * 2) = hh;
            *(uint32_t*)(QPl + (w16 + gid) * AP + j * 8 + tig * 2) = ll;
            split_pack(p2, p3, hh, ll);
            *(uint32_t*)(QPh + (w16 + gid + 8) * AP + j * 8 + tig * 2) = hh;
            *(uint32_t*)(QPl + (w16 + gid + 8) * AP + j * 8 + tig * 2) = ll;
        }
        rs0 += __shfl_xor_sync(~0u, rs0, 1);
        rs0 += __shfl_xor_sync(~0u, rs0, 2);
        rs1 += __shfl_xor_sync(~0u, rs1, 1);
        rs1 += __shfl_xor_sync(~0u, rs1, 2);
        l0 = l0 * a0 + rs0;
        l1 = l1 * a1 + rs1;
#pragma unroll
        for (int j = 0; j < 8; ++j) {
            O[j][0] *= a0; O[j][1] *= a0; O[j][2] *= a1; O[j][3] *= a1;
        }
        __syncwarp();   // P rows are warp-private

        // O += P @ V (V^T frags via ldmatrix.trans)
#pragma unroll
        for (int ks = 0; ks < 4; ++ks) {
            uint32_t pah[4], pal[4];
            const uint32_t pro = (uint32_t)((w16 * AP + ks * 16) * 2);
            ldsmA(pah, QPh_u + pro, AP * 2);
            ldsmA(pal, QPl_u + pro, AP * 2);
            uint32_t vh[8][2], vl[8][2];
#pragma unroll
            for (int db = 0; db < 4; ++db) {
                const uint32_t ro = (uint32_t)((ks * 16 * AP + db * 16) * 2);
                uint32_t t[4];
                ldsmAT(t, Vh_u + ro, AP * 2);
                vh[db * 2][0] = t[0]; vh[db * 2][1] = t[1];
                vh[db * 2 + 1][0] = t[2]; vh[db * 2 + 1][1] = t[3];
                ldsmAT(t, Vl_u + ro, AP * 2);
                vl[db * 2][0] = t[0]; vl[db * 2][1] = t[1];
                vl[db * 2 + 1][0] = t[2]; vl[db * 2 + 1][1] = t[3];
            }
#pragma unroll
            for (int j = 0; j < 8; ++j) {
                mma16(O[j], pah, vh[j]);
                mma16(O[j], pah, vl[j]);
                mma16(O[j], pal, vh[j]);
            }
        }

        // store next tile into the alternate buffer; one sync per iteration.
        // (Writing buf (jt+1)&1 is safe: it was last read before the sync that
        // ended iteration jt-1.)
        if (jt + 1 < NT) { storKV((jt + 1) & 1); __syncthreads(); }
    }

    // Epilogue
    const float i0 = 1.f / l0, i1 = 1.f / l1;
    float* d0 = ao + ((size_t)b * NSEQ + qt * 128 + w16 + gid) * DIMM + h * DHEAD;
    float* d1 = d0 + 8 * DIMM;
#pragma unroll
    for (int j = 0; j < 8; ++j) {
        const int col = j * 8 + tig * 2;
        *(float2*)(d0 + col) = make_float2(O[j][0] * i0, O[j][1] * i0);
        *(float2*)(d1 + col) = make_float2(O[j][2] * i1, O[j][3] * i1);
    }
}

// ---------------------------------------------------------------------------
extern "C" void kernel_launch(void* const* d_in, const int* in_sizes, int n_in,
                              void* d_out, int out_size)
{
    const float* x     = (const float*)d_in[0];
    const float* w_qkv = (const float*)d_in[1];
    const float* w_out = (const float*)d_in[2];
    const float* b_out = (const float*)d_in[3];
    float* out = (float*)d_out;

    float *qkv, *ao;
    __nv_bfloat16 *wqh, *wql, *woh, *wol;
    cudaGetSymbolAddress((void**)&qkv, g_qkv);
    cudaGetSymbolAddress((void**)&ao, g_ao);
    cudaGetSymbolAddress((void**)&wqh, g_wqkvT_hi);
    cudaGetSymbolAddress((void**)&wql, g_wqkvT_lo);
    cudaGetSymbolAddress((void**)&woh, g_woutT_hi);
    cudaGetSymbolAddress((void**)&wol, g_woutT_lo);

    const int M = NB * NSEQ;   // 8192

    // 0) transpose + split weights
    transpose_split<<<dim3(QKVC / 32, DIMM / 32), dim3(32, 8)>>>(w_qkv, wqh, wql, DIMM, QKVC);
    transpose_split<<<dim3(DIMM / 32, DIMM / 32), dim3(32, 8)>>>(w_out, woh, wol, DIMM, DIMM);

    // 1) QKV projection
    const int gsmem = 2 * 4 * GPLANE * (int)sizeof(__nv_bfloat16);
    cudaFuncSetAttribute(gemm_bf16x3<false>, cudaFuncAttributeMaxDynamicSharedMemorySize, gsmem);
    cudaFuncSetAttribute(gemm_bf16x3<true>,  cudaFuncAttributeMaxDynamicSharedMemorySize, gsmem);
    gemm_bf16x3<false><<<dim3(QKVC / 128, M / 128), 256, gsmem>>>(x, wqh, wql, nullptr, qkv, M, QKVC, DIMM);

    // 2) Flash attention
    const int asmem = (2 * APLANE_Q + 2 * KVBUF) * (int)sizeof(__nv_bfloat16);   // 110592
    cudaFuncSetAttribute(attn_bf16x3, cudaFuncAttributeMaxDynamicSharedMemorySize, asmem);
    attn_bf16x3<<<dim3(NSEQ / 128, NH, NB), 256, asmem>>>(qkv, ao);

    // 3) Output projection + bias
    gemm_bf16x3<true><<<dim3(DIMM / 128, M / 128), 256, gsmem>>>(ao, woh, wol, b_out, out, M, DIMM, DIMM);
}